// round 1
// baseline (speedup 1.0000x reference)
#include <cuda_runtime.h>
#include <math.h>

#define EMB 1024
#define HID 1024
#define BATCH 64
#define SEQ 512

typedef unsigned long long ull;

// persistent hidden state + grid barrier counter
__device__ float g_h[BATCH * HID];
__device__ unsigned g_count;

__device__ __forceinline__ void ffma2(ull& d, ull a, ull b) {
    asm("fma.rn.f32x2 %0, %1, %2, %0;" : "+l"(d) : "l"(a), "l"(b));
}
__device__ __forceinline__ float ull_lo(ull x) { return __uint_as_float((unsigned)x); }
__device__ __forceinline__ float ull_hi(ull x) { return __uint_as_float((unsigned)(x >> 32)); }

// ---------------- init: zero h0 and barrier counter (every launch -> deterministic) ----------------
__global__ void init_kernel() {
    int i = blockIdx.x * blockDim.x + threadIdx.x;
    if (i < BATCH * HID / 4) ((float4*)g_h)[i] = make_float4(0.f, 0.f, 0.f, 0.f);
    if (i == 0) g_count = 0u;
}

// ---------------- x_proj GEMM ----------------
// out[(s*64+b)*1024 + j] = sum_e embeds[(b*512+s)*1024+e] * W_ih[j*1024+e] + b_ih[j] + b_hh[j]
#define BM 128
#define BN 128
#define BK 8
#define APAD 260   // duplicated A row: 256 floats + 4 pad (keeps 16B align, breaks bank repeat)
#define BPAD 132

__global__ __launch_bounds__(256) void xproj_kernel(
    const float* __restrict__ E, const float* __restrict__ Wih,
    const float* __restrict__ bih, const float* __restrict__ bhh,
    float* __restrict__ out)
{
    __shared__ __align__(16) float Asd[BK * APAD];  // A duplicated per element: {a,a}
    __shared__ __align__(16) float Bs[BK * BPAD];

    const int tid = threadIdx.x;
    const int mt = blockIdx.y * BM;
    const int nt = blockIdx.x * BN;
    const int tx = tid & 15;   // j direction
    const int ty = tid >> 4;   // m direction

    const int lrow = tid >> 1;
    const int lh = tid & 1;

    const float* Aptr = E + (size_t)(mt + lrow) * EMB + 4 * lh;
    const float* Bptr = Wih + (size_t)(nt + lrow) * EMB + 4 * lh;

    ull acc[8][4];
#pragma unroll
    for (int m = 0; m < 8; m++)
#pragma unroll
        for (int p = 0; p < 4; p++) acc[m][p] = 0ull;

    float4 av = *(const float4*)(Aptr);
    float4 bv = *(const float4*)(Bptr);

    auto store_tile = [&](const float4& a4, const float4& b4) {
        float ar[4] = {a4.x, a4.y, a4.z, a4.w};
        float br[4] = {b4.x, b4.y, b4.z, b4.w};
#pragma unroll
        for (int i = 0; i < 4; i++) {
            int k = 4 * lh + i;
            *(float2*)&Asd[k * APAD + lrow * 2] = make_float2(ar[i], ar[i]);
            Bs[k * BPAD + lrow] = br[i];
        }
    };

    auto compute_tile = [&]() {
#pragma unroll
        for (int k = 0; k < BK; k++) {
            ulonglong2 b01 = *(const ulonglong2*)&Bs[k * BPAD + tx * 8];
            ulonglong2 b23 = *(const ulonglong2*)&Bs[k * BPAD + tx * 8 + 4];
            ulonglong2 a0 = *(const ulonglong2*)&Asd[k * APAD + ty * 16];
            ulonglong2 a1 = *(const ulonglong2*)&Asd[k * APAD + ty * 16 + 4];
            ulonglong2 a2 = *(const ulonglong2*)&Asd[k * APAD + ty * 16 + 8];
            ulonglong2 a3 = *(const ulonglong2*)&Asd[k * APAD + ty * 16 + 12];
            ull ad[8] = {a0.x, a0.y, a1.x, a1.y, a2.x, a2.y, a3.x, a3.y};
            ull bp[4] = {b01.x, b01.y, b23.x, b23.y};
#pragma unroll
            for (int m = 0; m < 8; m++)
#pragma unroll
                for (int p = 0; p < 4; p++)
                    ffma2(acc[m][p], ad[m], bp[p]);
        }
    };

    store_tile(av, bv);
    __syncthreads();

    for (int kt = 0; kt < EMB / BK - 1; kt++) {
        av = *(const float4*)(Aptr + (kt + 1) * BK);
        bv = *(const float4*)(Bptr + (kt + 1) * BK);
        compute_tile();
        __syncthreads();
        store_tile(av, bv);
        __syncthreads();
    }
    compute_tile();

    // epilogue: bias add, (b,s)->(s,b) layout swap, vector stores
    const int jb = nt + tx * 8;
    float4 u0 = *(const float4*)&bih[jb];
    float4 u1 = *(const float4*)&bih[jb + 4];
    float4 v0 = *(const float4*)&bhh[jb];
    float4 v1 = *(const float4*)&bhh[jb + 4];
    float bias[8] = {u0.x + v0.x, u0.y + v0.y, u0.z + v0.z, u0.w + v0.w,
                     u1.x + v1.x, u1.y + v1.y, u1.z + v1.z, u1.w + v1.w};
#pragma unroll
    for (int m = 0; m < 8; m++) {
        int gm = mt + ty * 8 + m;
        int bb = gm >> 9;      // batch
        int ss = gm & 511;     // seq
        float r[8];
#pragma unroll
        for (int p = 0; p < 4; p++) {
            r[2 * p]     = ull_lo(acc[m][p]) + bias[2 * p];
            r[2 * p + 1] = ull_hi(acc[m][p]) + bias[2 * p + 1];
        }
        float* orow = out + (size_t)(ss * 64 + bb) * HID + jb;
        *(float4*)orow = make_float4(r[0], r[1], r[2], r[3]);
        *(float4*)(orow + 4) = make_float4(r[4], r[5], r[6], r[7]);
    }
}

// ---------------- sequential scan (persistent kernel + software grid barrier) ----------------
// grid = 32 j-groups x 4 b-groups = 128 CTAs (all co-resident: 1 CTA/SM at this smem size)
#define GJ 32
#define JT 32
#define BT 16
#define WPAD 1028
#define SCAN_SMEM ((JT * WPAD + BT * HID + 512 * 8) * 4)

__global__ __launch_bounds__(256, 1) void scan_kernel(
    const float* __restrict__ Whh, float* __restrict__ out)
{
    extern __shared__ __align__(16) float sm[];
    float* Wsm = sm;                  // [JT][WPAD] : W_hh slice, resident across all steps
    float* hsm = sm + JT * WPAD;      // [BT][HID]  : h_{t-1} stage
    float* red = hsm + BT * HID;      // [512][8]   : warp partials

    const int tid = threadIdx.x;
    const int cta = blockIdx.x;
    const int cj = cta & (GJ - 1);
    const int cb = cta >> 5;
    const int jbase = cj * JT;
    const int bbase = cb * BT;

    // load W slice once (rows jbase..jbase+31)
    for (int idx = tid; idx < JT * HID / 4; idx += 256) {
        int r = idx >> 8;
        int c = idx & 255;
        float4 w = *(const float4*)&Whh[(size_t)(jbase + r) * HID + c * 4];
        *(float4*)&Wsm[r * WPAD + c * 4] = w;
    }

    const int j = tid & 31;       // output column within slice
    const int w = tid >> 5;       // warp = k-chunk
    const int k0 = w * 128;
    const unsigned nCTA = gridDim.x;

    for (int t = 0; t < SEQ; t++) {
        // stage h_{t-1} rows for our batches (L2, bypass L1: other SMs wrote it)
        for (int idx = tid; idx < BT * HID / 4; idx += 256) {
            int r = idx >> 8;
            int c = idx & 255;
            float4 h = __ldcg((const float4*)&g_h[(size_t)(bbase + r) * HID + c * 4]);
            *(float4*)&hsm[r * HID + c * 4] = h;
        }
        __syncthreads();

        ull acc[BT];
#pragma unroll
        for (int b = 0; b < BT; b++) acc[b] = 0ull;

        const float* wrow = &Wsm[j * WPAD + k0];
#pragma unroll 4
        for (int kk = 0; kk < 128; kk += 4) {
            ulonglong2 wv = *(const ulonglong2*)(wrow + kk);
#pragma unroll
            for (int b = 0; b < BT; b++) {
                ulonglong2 hv = *(const ulonglong2*)&hsm[b * HID + k0 + kk];
                ffma2(acc[b], wv.x, hv.x);
                ffma2(acc[b], wv.y, hv.y);
            }
        }

#pragma unroll
        for (int b = 0; b < BT; b++)
            red[(b * 32 + j) * 8 + w] = ull_lo(acc[b]) + ull_hi(acc[b]);
        __syncthreads();

        for (int o = tid; o < 512; o += 256) {
            float4 p0 = *(const float4*)&red[o * 8];
            float4 p1 = *(const float4*)&red[o * 8 + 4];
            float s = ((p0.x + p0.y) + (p0.z + p0.w)) + ((p1.x + p1.y) + (p1.z + p1.w));
            int bl = o >> 5, jj = o & 31;
            int bg = bbase + bl, jg = jbase + jj;
            size_t oi = (size_t)(t * 64 + bg) * HID + jg;
            float val = tanhf(out[oi] + s);   // out holds x_proj(+biases) for this (t,b,j)
            out[oi] = val;
            __stcg(&g_h[(size_t)bg * HID + jg], val);
        }

        // grid barrier (monotonic counter: no reset race; init kernel zeroes per launch)
        __threadfence();
        __syncthreads();
        if (tid == 0) {
            atomicAdd(&g_count, 1u);
            unsigned target = nCTA * (unsigned)(t + 1);
            volatile unsigned* p = &g_count;
            while (*p < target) { }
        }
        __syncthreads();
    }
}

// ---------------- launch ----------------
extern "C" void kernel_launch(void* const* d_in, const int* in_sizes, int n_in,
                              void* d_out, int out_size) {
    const float* embeds = (const float*)d_in[0];
    const float* W_ih   = (const float*)d_in[1];
    const float* W_hh   = (const float*)d_in[2];
    const float* b_ih   = (const float*)d_in[3];
    const float* b_hh   = (const float*)d_in[4];
    float* out = (float*)d_out;

    cudaFuncSetAttribute(scan_kernel, cudaFuncAttributeMaxDynamicSharedMemorySize, SCAN_SMEM);

    init_kernel<<<64, 256>>>();
    dim3 grid(EMB / BN, (BATCH * SEQ) / BM);   // (8, 256)
    xproj_kernel<<<grid, 256>>>(embeds, W_ih, b_ih, b_hh, out);
    scan_kernel<<<128, 256, SCAN_SMEM>>>(W_hh, out);
}

// round 9
// speedup vs baseline: 1.1843x; 1.1843x over previous
#include <cuda_runtime.h>
#include <math.h>

#define EMB 1024
#define HID 1024
#define BATCH 64
#define SEQ 512

typedef unsigned long long ull;

// double-buffered hidden state (read t&1, write (t+1)&1) + per-bgroup barrier counters
__device__ float g_h[2][BATCH * HID];
struct Cnt { unsigned v; unsigned pad[31]; };
__device__ Cnt g_cnt[4];

__device__ __forceinline__ void ffma2(ull& d, ull a, ull b) {
    asm("fma.rn.f32x2 %0, %1, %2, %0;" : "+l"(d) : "l"(a), "l"(b));
}
__device__ __forceinline__ float ull_lo(ull x) { return __uint_as_float((unsigned)x); }
__device__ __forceinline__ float ull_hi(ull x) { return __uint_as_float((unsigned)(x >> 32)); }

__device__ __forceinline__ float ftanh(float x) {
    float ax = fabsf(x);
    float e = __expf(-2.0f * ax);
    float r = (1.0f - e) / (1.0f + e);
    return copysignf(r, x);
}

// ---------------- init: zero h0 (buffer 0) and barrier counters (every launch -> deterministic) ----------------
__global__ void init_kernel() {
    int i = blockIdx.x * blockDim.x + threadIdx.x;
    if (i < BATCH * HID / 4) ((float4*)g_h[0])[i] = make_float4(0.f, 0.f, 0.f, 0.f);
    if (i < 4) g_cnt[i].v = 0u;
}

// ---------------- x_proj GEMM (double-buffered, 1 sync/tile) ----------------
// out[(s*64+b)*1024 + j] = sum_e embeds[(b*512+s)*1024+e] * W_ih[j*1024+e] + b_ih[j] + b_hh[j]
#define BM 128
#define BN 128
#define BK 8
#define APAD 260
#define BPAD 132

__global__ __launch_bounds__(256) void xproj_kernel(
    const float* __restrict__ E, const float* __restrict__ Wih,
    const float* __restrict__ bih, const float* __restrict__ bhh,
    float* __restrict__ out)
{
    __shared__ __align__(16) float Asd[2][BK * APAD];  // A duplicated per element: {a,a}
    __shared__ __align__(16) float Bs[2][BK * BPAD];

    const int tid = threadIdx.x;
    const int mt = blockIdx.y * BM;
    const int nt = blockIdx.x * BN;
    const int tx = tid & 15;   // j direction
    const int ty = tid >> 4;   // m direction

    const int lrow = tid >> 1;
    const int lh = tid & 1;

    const float* Aptr = E + (size_t)(mt + lrow) * EMB + 4 * lh;
    const float* Bptr = Wih + (size_t)(nt + lrow) * EMB + 4 * lh;

    ull acc[8][4];
#pragma unroll
    for (int m = 0; m < 8; m++)
#pragma unroll
        for (int p = 0; p < 4; p++) acc[m][p] = 0ull;

    auto store_tile = [&](int buf, const float4& a4, const float4& b4) {
        float ar[4] = {a4.x, a4.y, a4.z, a4.w};
        float br[4] = {b4.x, b4.y, b4.z, b4.w};
#pragma unroll
        for (int i = 0; i < 4; i++) {
            int k = 4 * lh + i;
            *(float2*)&Asd[buf][k * APAD + lrow * 2] = make_float2(ar[i], ar[i]);
            Bs[buf][k * BPAD + lrow] = br[i];
        }
    };

    auto compute_tile = [&](int buf) {
#pragma unroll
        for (int k = 0; k < BK; k++) {
            ulonglong2 b01 = *(const ulonglong2*)&Bs[buf][k * BPAD + tx * 8];
            ulonglong2 b23 = *(const ulonglong2*)&Bs[buf][k * BPAD + tx * 8 + 4];
            ulonglong2 a0 = *(const ulonglong2*)&Asd[buf][k * APAD + ty * 16];
            ulonglong2 a1 = *(const ulonglong2*)&Asd[buf][k * APAD + ty * 16 + 4];
            ulonglong2 a2 = *(const ulonglong2*)&Asd[buf][k * APAD + ty * 16 + 8];
            ulonglong2 a3 = *(const ulonglong2*)&Asd[buf][k * APAD + ty * 16 + 12];
            ull ad[8] = {a0.x, a0.y, a1.x, a1.y, a2.x, a2.y, a3.x, a3.y};
            ull bp[4] = {b01.x, b01.y, b23.x, b23.y};
#pragma unroll
            for (int m = 0; m < 8; m++)
#pragma unroll
                for (int p = 0; p < 4; p++)
                    ffma2(acc[m][p], ad[m], bp[p]);
        }
    };

    float4 av = *(const float4*)(Aptr);
    float4 bv = *(const float4*)(Bptr);
    store_tile(0, av, bv);
    __syncthreads();

    const int NT = EMB / BK;   // 128 tiles
    for (int kt = 0; kt < NT - 1; kt++) {
        av = *(const float4*)(Aptr + (kt + 1) * BK);
        bv = *(const float4*)(Bptr + (kt + 1) * BK);
        compute_tile(kt & 1);
        store_tile((kt + 1) & 1, av, bv);
        __syncthreads();
    }
    compute_tile((NT - 1) & 1);

    // epilogue: bias add, (b,s)->(s,b) layout swap, vector stores
    const int jb = nt + tx * 8;
    float4 u0 = *(const float4*)&bih[jb];
    float4 u1 = *(const float4*)&bih[jb + 4];
    float4 v0 = *(const float4*)&bhh[jb];
    float4 v1 = *(const float4*)&bhh[jb + 4];
    float bias[8] = {u0.x + v0.x, u0.y + v0.y, u0.z + v0.z, u0.w + v0.w,
                     u1.x + v1.x, u1.y + v1.y, u1.z + v1.z, u1.w + v1.w};
#pragma unroll
    for (int m = 0; m < 8; m++) {
        int gm = mt + ty * 8 + m;
        int bb = gm >> 9;      // batch
        int ss = gm & 511;     // seq
        float r[8];
#pragma unroll
        for (int p = 0; p < 4; p++) {
            r[2 * p]     = ull_lo(acc[m][p]) + bias[2 * p];
            r[2 * p + 1] = ull_hi(acc[m][p]) + bias[2 * p + 1];
        }
        float* orow = out + (size_t)(ss * 64 + bb) * HID + jb;
        *(float4*)orow = make_float4(r[0], r[1], r[2], r[3]);
        *(float4*)(orow + 4) = make_float4(r[4], r[5], r[6], r[7]);
    }
}

// ---------------- sequential scan ----------------
// grid = 32 j-groups x 4 b-groups = 128 CTAs, 1 CTA/SM (smem-bound)
// barrier is per-b-group (32 CTAs) with release/acquire atomics.
// g_h is double-buffered: step t reads buf t&1, writes buf (t+1)&1 -> no read/write race across skewed CTAs.
#define GJ 32
#define JT 32
#define BT 16
#define WPAD 1028
#define SCAN_SMEM ((JT * WPAD + BT * HID + 8 * 512) * 4)

__global__ __launch_bounds__(256, 1) void scan_kernel(
    const float* __restrict__ Whh, float* __restrict__ out)
{
    extern __shared__ __align__(16) float sm[];
    float* Wsm = sm;                  // [JT][WPAD] : W_hh slice, resident across all steps
    float* hsm = sm + JT * WPAD;      // [BT][HID]  : h_{t-1} stage (warp-private k-slices)
    float* red = hsm + BT * HID;      // [8][512]   : warp partials, conflict-free

    const int tid = threadIdx.x;
    const int cta = blockIdx.x;
    const int cj = cta & (GJ - 1);
    const int cb = cta >> 5;
    const int jbase = cj * JT;
    const int bbase = cb * BT;

    // load W slice once (rows jbase..jbase+31)
    for (int idx = tid; idx < JT * HID / 4; idx += 256) {
        int r = idx >> 8;
        int c = idx & 255;
        float4 w = *(const float4*)&Whh[(size_t)(jbase + r) * HID + c * 4];
        *(float4*)&Wsm[r * WPAD + c * 4] = w;
    }

    const int j = tid & 31;       // lane = output column within slice
    const int w = tid >> 5;       // warp = k-chunk
    const int k0 = w * 128;

    unsigned* cnt = &g_cnt[cb].v;

    // epilogue output indices for this thread
    const int o1 = tid, o2 = tid + 256;
    const int b1 = o1 >> 5, j1 = o1 & 31;
    const int b2 = o2 >> 5, j2 = o2 & 31;
    const size_t hoff1 = (size_t)(bbase + b1) * HID + jbase + j1;
    const size_t hoff2 = (size_t)(bbase + b2) * HID + jbase + j2;
    // out index for step t: ((t*64 + bbase + b) << 10) + jbase + jj
    size_t ooff1 = (size_t)((bbase + b1) << 10) + jbase + j1;
    size_t ooff2 = (size_t)((bbase + b2) << 10) + jbase + j2;

    // prefetch xp for t=0
    float xp0 = out[ooff1];
    float xp1 = out[ooff2];

    __syncthreads();  // Wsm ready

    for (int t = 0; t < SEQ; t++) {
        const float* hrd = g_h[t & 1];        // read buffer
        float* hwr = g_h[(t + 1) & 1];        // write buffer

        // stage this warp's k-slice of h_{t-1} (L2, bypass L1)
        {
            const float* hsrc = hrd + (size_t)bbase * HID + k0 + 4 * j;
            float* hdst = &hsm[k0 + 4 * j];
            float4 tmp[8];
#pragma unroll
            for (int b = 0; b < 8; b++)
                tmp[b] = __ldcg((const float4*)(hsrc + (size_t)b * HID));
#pragma unroll
            for (int b = 0; b < 8; b++)
                *(float4*)(hdst + (size_t)b * HID) = tmp[b];
#pragma unroll
            for (int b = 0; b < 8; b++)
                tmp[b] = __ldcg((const float4*)(hsrc + (size_t)(b + 8) * HID));
#pragma unroll
            for (int b = 0; b < 8; b++)
                *(float4*)(hdst + (size_t)(b + 8) * HID) = tmp[b];
        }
        __syncwarp();

        ull acc[BT];
#pragma unroll
        for (int b = 0; b < BT; b++) acc[b] = 0ull;

        const float* wrow = &Wsm[j * WPAD + k0];
#pragma unroll 4
        for (int kk = 0; kk < 128; kk += 4) {
            ulonglong2 wv = *(const ulonglong2*)(wrow + kk);
#pragma unroll
            for (int b = 0; b < BT; b++) {
                ulonglong2 hv = *(const ulonglong2*)&hsm[b * HID + k0 + kk];
                ffma2(acc[b], wv.x, hv.x);
                ffma2(acc[b], wv.y, hv.y);
            }
        }

        // partials: red[w][b*32 + j]  (writes consecutive within warp -> conflict-free)
#pragma unroll
        for (int b = 0; b < BT; b++)
            red[w * 512 + b * 32 + j] = ull_lo(acc[b]) + ull_hi(acc[b]);
        __syncthreads();

        // epilogue: 2 outputs per thread, xp already in regs
        float s0 = 0.f, s1 = 0.f;
#pragma unroll
        for (int ww = 0; ww < 8; ww++) {
            s0 += red[ww * 512 + o1];
            s1 += red[ww * 512 + o2];
        }
        float v0 = ftanh(xp0 + s0);
        float v1 = ftanh(xp1 + s1);
        size_t toff = (size_t)t << 16;  // t*64*1024
        out[toff + ooff1] = v0;
        out[toff + ooff2] = v1;
        __stcg(&hwr[hoff1], v0);
        __stcg(&hwr[hoff2], v1);

        __syncthreads();  // all h stores in CTA done before the release-arrive
        if (tid == 0)
            asm volatile("red.release.gpu.global.add.u32 [%0], 1;" :: "l"(cnt) : "memory");

        // prefetch xp for t+1 while waiting
        if (t + 1 < SEQ) {
            size_t toff2 = (size_t)(t + 1) << 16;
            xp0 = out[toff2 + ooff1];
            xp1 = out[toff2 + ooff2];
        }

        if (tid == 0) {
            unsigned target = (unsigned)(GJ * (t + 1));
            unsigned v;
            do {
                asm volatile("ld.acquire.gpu.global.u32 %0, [%1];" : "=r"(v) : "l"(cnt) : "memory");
            } while (v < target);
        }
        __syncthreads();
    }
}

// ---------------- launch ----------------
extern "C" void kernel_launch(void* const* d_in, const int* in_sizes, int n_in,
                              void* d_out, int out_size) {
    const float* embeds = (const float*)d_in[0];
    const float* W_ih   = (const float*)d_in[1];
    const float* W_hh   = (const float*)d_in[2];
    const float* b_ih   = (const float*)d_in[3];
    const float* b_hh   = (const float*)d_in[4];
    float* out = (float*)d_out;

    cudaFuncSetAttribute(scan_kernel, cudaFuncAttributeMaxDynamicSharedMemorySize, SCAN_SMEM);

    init_kernel<<<64, 256>>>();
    dim3 grid(EMB / BN, (BATCH * SEQ) / BM);   // (8, 256)
    xproj_kernel<<<grid, 256>>>(embeds, W_ih, b_ih, b_hh, out);
    scan_kernel<<<128, 256, SCAN_SMEM>>>(W_hh, out);
}

// round 12
// speedup vs baseline: 1.2229x; 1.0326x over previous
#include <cuda_runtime.h>
#include <math.h>

#define EMB 1024
#define HID 1024
#define BATCH 64
#define SEQ 512

typedef unsigned long long ull;

// double-buffered hidden state (read t&1, write (t+1)&1) + per-bgroup barrier counters
__device__ float g_h[2][BATCH * HID];
struct Cnt { unsigned v; unsigned pad[31]; };
__device__ Cnt g_cnt[4];

__device__ __forceinline__ void ffma2(ull& d, ull a, ull b) {
    asm("fma.rn.f32x2 %0, %1, %2, %0;" : "+l"(d) : "l"(a), "l"(b));
}
__device__ __forceinline__ float ull_lo(ull x) { return __uint_as_float((unsigned)x); }
__device__ __forceinline__ float ull_hi(ull x) { return __uint_as_float((unsigned)(x >> 32)); }

__device__ __forceinline__ float ftanh(float x) {
    float ax = fabsf(x);
    float e = __expf(-2.0f * ax);
    float r = (1.0f - e) / (1.0f + e);
    return copysignf(r, x);
}

// ---------------- x_proj GEMM (double-buffered, 1 sync/tile) + embedded init ----------------
// out[(s*64+b)*1024 + j] = sum_e embeds[(b*512+s)*1024+e] * W_ih[j*1024+e] + b_ih[j] + b_hh[j]
// Init of g_h[0] and g_cnt is folded in here (blockIdx.x==0 blocks) so kernel_launch has
// exactly 2 launches -> ncu's fixed "-s 5" lands on scan_kernel.
#define BM 128
#define BN 128
#define BK 8
#define APAD 260
#define BPAD 132

__global__ __launch_bounds__(256) void xproj_kernel(
    const float* __restrict__ E, const float* __restrict__ Wih,
    const float* __restrict__ bih, const float* __restrict__ bhh,
    float* __restrict__ out)
{
    // embedded init: zero h0 (buffer 0) and barrier counters; scan is stream-ordered after us
    if (blockIdx.x == 0) {
        if (blockIdx.y < 64) {
            int i = blockIdx.y * 256 + threadIdx.x;          // 0..16383
            ((float4*)g_h[0])[i] = make_float4(0.f, 0.f, 0.f, 0.f);
        }
        if (blockIdx.y == 64 && threadIdx.x < 4) g_cnt[threadIdx.x].v = 0u;
    }

    __shared__ __align__(16) float Asd[2][BK * APAD];  // A duplicated per element: {a,a}
    __shared__ __align__(16) float Bs[2][BK * BPAD];

    const int tid = threadIdx.x;
    const int mt = blockIdx.y * BM;
    const int nt = blockIdx.x * BN;
    const int tx = tid & 15;   // j direction
    const int ty = tid >> 4;   // m direction

    const int lrow = tid >> 1;
    const int lh = tid & 1;

    const float* Aptr = E + (size_t)(mt + lrow) * EMB + 4 * lh;
    const float* Bptr = Wih + (size_t)(nt + lrow) * EMB + 4 * lh;

    ull acc[8][4];
#pragma unroll
    for (int m = 0; m < 8; m++)
#pragma unroll
        for (int p = 0; p < 4; p++) acc[m][p] = 0ull;

    auto store_tile = [&](int buf, const float4& a4, const float4& b4) {
        float ar[4] = {a4.x, a4.y, a4.z, a4.w};
        float br[4] = {b4.x, b4.y, b4.z, b4.w};
#pragma unroll
        for (int i = 0; i < 4; i++) {
            int k = 4 * lh + i;
            *(float2*)&Asd[buf][k * APAD + lrow * 2] = make_float2(ar[i], ar[i]);
            Bs[buf][k * BPAD + lrow] = br[i];
        }
    };

    auto compute_tile = [&](int buf) {
#pragma unroll
        for (int k = 0; k < BK; k++) {
            ulonglong2 b01 = *(const ulonglong2*)&Bs[buf][k * BPAD + tx * 8];
            ulonglong2 b23 = *(const ulonglong2*)&Bs[buf][k * BPAD + tx * 8 + 4];
            ulonglong2 a0 = *(const ulonglong2*)&Asd[buf][k * APAD + ty * 16];
            ulonglong2 a1 = *(const ulonglong2*)&Asd[buf][k * APAD + ty * 16 + 4];
            ulonglong2 a2 = *(const ulonglong2*)&Asd[buf][k * APAD + ty * 16 + 8];
            ulonglong2 a3 = *(const ulonglong2*)&Asd[buf][k * APAD + ty * 16 + 12];
            ull ad[8] = {a0.x, a0.y, a1.x, a1.y, a2.x, a2.y, a3.x, a3.y};
            ull bp[4] = {b01.x, b01.y, b23.x, b23.y};
#pragma unroll
            for (int m = 0; m < 8; m++)
#pragma unroll
                for (int p = 0; p < 4; p++)
                    ffma2(acc[m][p], ad[m], bp[p]);
        }
    };

    float4 av = *(const float4*)(Aptr);
    float4 bv = *(const float4*)(Bptr);
    store_tile(0, av, bv);
    __syncthreads();

    const int NT = EMB / BK;   // 128 tiles
    for (int kt = 0; kt < NT - 1; kt++) {
        av = *(const float4*)(Aptr + (kt + 1) * BK);
        bv = *(const float4*)(Bptr + (kt + 1) * BK);
        compute_tile(kt & 1);
        store_tile((kt + 1) & 1, av, bv);
        __syncthreads();
    }
    compute_tile((NT - 1) & 1);

    // epilogue: bias add, (b,s)->(s,b) layout swap, vector stores
    const int jb = nt + tx * 8;
    float4 u0 = *(const float4*)&bih[jb];
    float4 u1 = *(const float4*)&bih[jb + 4];
    float4 v0 = *(const float4*)&bhh[jb];
    float4 v1 = *(const float4*)&bhh[jb + 4];
    float bias[8] = {u0.x + v0.x, u0.y + v0.y, u0.z + v0.z, u0.w + v0.w,
                     u1.x + v1.x, u1.y + v1.y, u1.z + v1.z, u1.w + v1.w};
#pragma unroll
    for (int m = 0; m < 8; m++) {
        int gm = mt + ty * 8 + m;
        int bb = gm >> 9;      // batch
        int ss = gm & 511;     // seq
        float r[8];
#pragma unroll
        for (int p = 0; p < 4; p++) {
            r[2 * p]     = ull_lo(acc[m][p]) + bias[2 * p];
            r[2 * p + 1] = ull_hi(acc[m][p]) + bias[2 * p + 1];
        }
        float* orow = out + (size_t)(ss * 64 + bb) * HID + jb;
        *(float4*)orow = make_float4(r[0], r[1], r[2], r[3]);
        *(float4*)(orow + 4) = make_float4(r[4], r[5], r[6], r[7]);
    }
}

// ---------------- sequential scan ----------------
// grid = 32 j-groups x 4 b-groups = 128 CTAs, 1 CTA/SM (smem-bound)
// barrier is per-b-group (32 CTAs) with release/acquire atomics.
// g_h double-buffered (read t&1, write (t+1)&1) -> no cross-CTA read/write race.
// Mainloop: 4j x 4b register tile per lane (lanes = 8 jg x 4 bg) -> 8 LDS.128 per
// 32 FFMA2 (was 17). W conflict-free, h broadcast per quarter-warp phase.
#define GJ 32
#define JT 32
#define BT 16
#define WPAD 1028
#define RSTRIDE 20                     // red j-stride (floats): float4 starts hit banks {0,4,...,28}
#define SCAN_SMEM ((JT * WPAD + BT * HID + 8 * JT * RSTRIDE) * 4)

__global__ __launch_bounds__(256, 1) void scan_kernel(
    const float* __restrict__ Whh, float* __restrict__ out)
{
    extern __shared__ __align__(16) float sm[];
    float* Wsm = sm;                  // [JT][WPAD] : W_hh slice, resident across all steps
    float* hsm = sm + JT * WPAD;      // [BT][HID]  : h_{t-1} stage (warp-private k-slices)
    float* red = hsm + BT * HID;      // [8][JT*RSTRIDE] : warp partials, red[w*640 + j*20 + b]

    const int tid = threadIdx.x;
    const int cta = blockIdx.x;
    const int cj = cta & (GJ - 1);
    const int cb = cta >> 5;
    const int jbase = cj * JT;
    const int bbase = cb * BT;

    // load W slice once (rows jbase..jbase+31)
    for (int idx = tid; idx < JT * HID / 4; idx += 256) {
        int r = idx >> 8;
        int c = idx & 255;
        float4 wv4 = *(const float4*)&Whh[(size_t)(jbase + r) * HID + c * 4];
        *(float4*)&Wsm[r * WPAD + c * 4] = wv4;
    }

    const int lane = tid & 31;
    const int w = tid >> 5;       // warp = k-chunk
    const int k0 = w * 128;
    const int bg = lane >> 3;     // 0..3 : b-group (constant per quarter-warp phase)
    const int jg = lane & 7;      // 0..7 : j-group

    unsigned* cnt = &g_cnt[cb].v;

    // epilogue output indices for this thread (o = b*32 + j)
    const int o1 = tid, o2 = tid + 256;
    const int b1 = o1 >> 5, j1 = o1 & 31;
    const int b2 = o2 >> 5, j2 = o2 & 31;
    const int ro1 = j1 * RSTRIDE + b1;
    const int ro2 = j2 * RSTRIDE + b2;
    const size_t hoff1 = (size_t)(bbase + b1) * HID + jbase + j1;
    const size_t hoff2 = (size_t)(bbase + b2) * HID + jbase + j2;
    size_t ooff1 = (size_t)((bbase + b1) << 10) + jbase + j1;
    size_t ooff2 = (size_t)((bbase + b2) << 10) + jbase + j2;

    // prefetch xp for t=0
    float xp0 = out[ooff1];
    float xp1 = out[ooff2];

    __syncthreads();  // Wsm ready

    const float* wbase = &Wsm[jg * WPAD + k0];          // + i*8*WPAD per j-step
    const float* hbase = &hsm[(bg * 4) * HID + k0];     // + ib*HID per b-step

    for (int t = 0; t < SEQ; t++) {
        const float* hrd = g_h[t & 1];
        float* hwr = g_h[(t + 1) & 1];

        // stage this warp's k-slice of h_{t-1} (L2, bypass L1)
        {
            const float* hsrc = hrd + (size_t)bbase * HID + k0 + 4 * lane;
            float* hdst = &hsm[k0 + 4 * lane];
            float4 tmp[8];
#pragma unroll
            for (int b = 0; b < 8; b++)
                tmp[b] = __ldcg((const float4*)(hsrc + (size_t)b * HID));
#pragma unroll
            for (int b = 0; b < 8; b++)
                *(float4*)(hdst + (size_t)b * HID) = tmp[b];
#pragma unroll
            for (int b = 0; b < 8; b++)
                tmp[b] = __ldcg((const float4*)(hsrc + (size_t)(b + 8) * HID));
#pragma unroll
            for (int b = 0; b < 8; b++)
                *(float4*)(hdst + (size_t)(b + 8) * HID) = tmp[b];
        }
        __syncwarp();

        // 4j x 4b register tile, f32x2 over k
        ull acc[4][4];
#pragma unroll
        for (int i = 0; i < 4; i++)
#pragma unroll
            for (int ib = 0; ib < 4; ib++) acc[i][ib] = 0ull;

#pragma unroll 2
        for (int kk = 0; kk < 128; kk += 4) {
            ulonglong2 wv[4], hv[4];
#pragma unroll
            for (int i = 0; i < 4; i++)
                wv[i] = *(const ulonglong2*)(wbase + i * 8 * WPAD + kk);
#pragma unroll
            for (int ib = 0; ib < 4; ib++)
                hv[ib] = *(const ulonglong2*)(hbase + ib * HID + kk);
#pragma unroll
            for (int i = 0; i < 4; i++)
#pragma unroll
                for (int ib = 0; ib < 4; ib++) {
                    ffma2(acc[i][ib], wv[i].x, hv[ib].x);
                    ffma2(acc[i][ib], wv[i].y, hv[ib].y);
                }
        }

        // partials: red[w*640 + j*20 + b], float4 over the lane's 4 b's (conflict-free)
#pragma unroll
        for (int i = 0; i < 4; i++) {
            int jj = jg + 8 * i;
            float4 p;
            p.x = ull_lo(acc[i][0]) + ull_hi(acc[i][0]);
            p.y = ull_lo(acc[i][1]) + ull_hi(acc[i][1]);
            p.z = ull_lo(acc[i][2]) + ull_hi(acc[i][2]);
            p.w = ull_lo(acc[i][3]) + ull_hi(acc[i][3]);
            *(float4*)&red[w * (JT * RSTRIDE) + jj * RSTRIDE + bg * 4] = p;
        }
        __syncthreads();

        // epilogue: 2 outputs per thread, xp already in regs
        float s0 = 0.f, s1 = 0.f;
#pragma unroll
        for (int ww = 0; ww < 8; ww++) {
            s0 += red[ww * (JT * RSTRIDE) + ro1];
            s1 += red[ww * (JT * RSTRIDE) + ro2];
        }
        float v0 = ftanh(xp0 + s0);
        float v1 = ftanh(xp1 + s1);
        size_t toff = (size_t)t << 16;  // t*64*1024
        out[toff + ooff1] = v0;
        out[toff + ooff2] = v1;
        __stcg(&hwr[hoff1], v0);
        __stcg(&hwr[hoff2], v1);

        __syncthreads();  // all h stores in CTA done before the release-arrive
        if (tid == 0)
            asm volatile("red.release.gpu.global.add.u32 [%0], 1;" :: "l"(cnt) : "memory");

        // prefetch xp for t+1 while waiting
        if (t + 1 < SEQ) {
            size_t toff2 = (size_t)(t + 1) << 16;
            xp0 = out[toff2 + ooff1];
            xp1 = out[toff2 + ooff2];
        }

        if (tid == 0) {
            unsigned target = (unsigned)(GJ * (t + 1));
            unsigned v;
            do {
                asm volatile("ld.acquire.gpu.global.u32 %0, [%1];" : "=r"(v) : "l"(cnt) : "memory");
            } while (v < target);
        }
        __syncthreads();
    }
}

// ---------------- launch ----------------
extern "C" void kernel_launch(void* const* d_in, const int* in_sizes, int n_in,
                              void* d_out, int out_size) {
    const float* embeds = (const float*)d_in[0];
    const float* W_ih   = (const float*)d_in[1];
    const float* W_hh   = (const float*)d_in[2];
    const float* b_ih   = (const float*)d_in[3];
    const float* b_hh   = (const float*)d_in[4];
    float* out = (float*)d_out;

    cudaFuncSetAttribute(scan_kernel, cudaFuncAttributeMaxDynamicSharedMemorySize, SCAN_SMEM);

    dim3 grid(EMB / BN, (BATCH * SEQ) / BM);   // (8, 256)
    xproj_kernel<<<grid, 256>>>(embeds, W_ih, b_ih, b_hh, out);   // also inits g_h/g_cnt
    scan_kernel<<<128, 256, SCAN_SMEM>>>(W_hh, out);
}